// round 5
// baseline (speedup 1.0000x reference)
#include <cuda_runtime.h>
#include <cuda_bf16.h>
#include <cstdint>

#define DD 128
#define MAX_N 100000
#define MAX_E 1600000
#define TILE_R 64
#define AS_STRIDE 132   // A tile row stride (floats): even -> b64-aligned, float4 ok
#define WT_STRIDE 130   // transposed-W col stride (floats): even -> b64-aligned

// Scratch (device globals — no allocation allowed)
__device__ float g_h[(size_t)MAX_N * DD];
__device__ float g_agg[(size_t)MAX_N * DD];
__device__ int   g_degi[MAX_N];
__device__ int   g_off[MAX_N + 1];
__device__ int   g_cursor[MAX_N];
__device__ int   g_bsum[1024];
__device__ int   g_csr[MAX_E];

// ---------------------------------------------------------------------------
__global__ void zero_degi_kernel(int* __restrict__ degi, int N) {
    int i = blockIdx.x * blockDim.x + threadIdx.x;
    if (i < N) degi[i] = 0;
}

__global__ void degi_kernel(const int* __restrict__ dst, int* __restrict__ degi, int E) {
    int e = blockIdx.x * blockDim.x + threadIdx.x;
    if (e < E) atomicAdd(degi + dst[e], 1);
}

// Block-local exclusive scan (Hillis-Steele in smem), emits block sums
__global__ void scan1_kernel(const int* __restrict__ degi, int* __restrict__ off,
                             int* __restrict__ bsum, int N) {
    __shared__ int s[256];
    int t = threadIdx.x;
    int i = blockIdx.x * 256 + t;
    int v = (i < N) ? degi[i] : 0;
    s[t] = v;
    __syncthreads();
#pragma unroll
    for (int d = 1; d < 256; d <<= 1) {
        int add = (t >= d) ? s[t - d] : 0;
        __syncthreads();
        s[t] += add;
        __syncthreads();
    }
    if (i < N) off[i] = s[t] - v;            // exclusive
    if (t == 255) bsum[blockIdx.x] = s[255]; // block total
}

__global__ void scan2_kernel(int* __restrict__ bsum, int nb) {
    __shared__ int s[512];
    int t = threadIdx.x;
    int v = (t < nb) ? bsum[t] : 0;
    s[t] = v;
    __syncthreads();
#pragma unroll
    for (int d = 1; d < 512; d <<= 1) {
        int add = (t >= d) ? s[t - d] : 0;
        __syncthreads();
        s[t] += add;
        __syncthreads();
    }
    if (t < nb) bsum[t] = s[t] - v;
}

__global__ void scan3_kernel(int* __restrict__ off, const int* __restrict__ bsum,
                             int N, int E) {
    int i = blockIdx.x * 256 + threadIdx.x;
    if (i < N) off[i] += bsum[blockIdx.x];
    if (i == 0) off[N] = E;
}

__global__ void place_kernel(const int* __restrict__ src, const int* __restrict__ dst,
                             int* __restrict__ cursor, int* __restrict__ csr, int E) {
    int e = blockIdx.x * blockDim.x + threadIdx.x;
    if (e >= E) return;
    int pos = atomicAdd(cursor + dst[e], 1);
    csr[pos] = src[e];
}

// h[n][:] = emb[annotation[n]][:]   (one warp per node, float4 lanes)
__global__ void embed_kernel(const int* __restrict__ ann,
                             const float4* __restrict__ emb,
                             float4* __restrict__ h, int N) {
    int gid = blockIdx.x * blockDim.x + threadIdx.x;
    int n = gid >> 5;
    int lane = gid & 31;
    if (n >= N) return;
    int a = __ldg(ann + n);
    h[(size_t)n * 32 + lane] = __ldg(emb + (size_t)a * 32 + lane);
}

// agg[n] = h[n] + sum_{s in in-neighbors(n)} h[s]   (warp per node, no atomics)
__global__ void gather_kernel(const float4* __restrict__ h,
                              float4* __restrict__ agg,
                              const int* __restrict__ off,
                              const int* __restrict__ csr, int N) {
    int gid = blockIdx.x * blockDim.x + threadIdx.x;
    int n = gid >> 5;
    int lane = gid & 31;
    if (n >= N) return;
    int beg = __ldg(off + n);
    int end = __ldg(off + n + 1);
    float4 acc = __ldg(h + (size_t)n * 32 + lane);   // self term
    int i = beg;
    for (; i + 8 <= end; i += 8) {
        int s[8];
#pragma unroll
        for (int j = 0; j < 8; j++) s[j] = __ldg(csr + i + j);
        float4 v[8];
#pragma unroll
        for (int j = 0; j < 8; j++) v[j] = __ldg(h + (size_t)s[j] * 32 + lane);
#pragma unroll
        for (int j = 0; j < 8; j++) {
            acc.x += v[j].x; acc.y += v[j].y; acc.z += v[j].z; acc.w += v[j].w;
        }
    }
    for (; i < end; i++) {
        int ss = __ldg(csr + i);
        float4 v = __ldg(h + (size_t)ss * 32 + lane);
        acc.x += v.x; acc.y += v.y; acc.z += v.z; acc.w += v.w;
    }
    agg[(size_t)n * 32 + lane] = acc;
}

// out[r][:] = relu( (agg[r][:] / (deg[r]+1)) @ W + b ),  deg from CSR offsets
// f32x2 packed-FMA GEMM: accumulators pack (even-k, odd-k) partial sums.
// Thread (tx,ty) handles rows {ty, ty+8, ..., ty+56} and cols {tx, tx+32, tx+64, tx+96}.
__global__ void layer_kernel(const float* __restrict__ agg,
                             const int* __restrict__ off,
                             const float* __restrict__ W,
                             const float* __restrict__ bias,
                             float* __restrict__ out, int N) {
    extern __shared__ float sh[];
    float* WshT = sh;                       // [c][k]: DD cols x WT_STRIDE
    float* Ash  = sh + DD * WT_STRIDE;      // TILE_R x AS_STRIDE

    int tx = threadIdx.x;                   // 0..31
    int ty = threadIdx.y;                   // 0..7
    int tid = ty * 32 + tx;
    int r0 = blockIdx.x * TILE_R;

    // Load W transposed into smem: W[k][c] -> WshT[c*WT_STRIDE + k]
    {
        const float4* Wg = (const float4*)W;
#pragma unroll
        for (int j = 0; j < (DD * DD / 4) / 256; j++) {
            int idx = tid + j * 256;        // = k*32 + c4
            int k  = idx >> 5;
            int c4 = idx & 31;
            float4 v = __ldg(Wg + idx);
            WshT[(c4 * 4 + 0) * WT_STRIDE + k] = v.x;
            WshT[(c4 * 4 + 1) * WT_STRIDE + k] = v.y;
            WshT[(c4 * 4 + 2) * WT_STRIDE + k] = v.z;
            WshT[(c4 * 4 + 3) * WT_STRIDE + k] = v.w;
        }
    }
    // Load A tile
    {
#pragma unroll
        for (int j = 0; j < (TILE_R * 32) / 256; j++) {
            int idx = tid + j * 256;
            int row = idx >> 5;
            int c4  = idx & 31;
            float4 v = make_float4(0.f, 0.f, 0.f, 0.f);
            if (r0 + row < N)
                v = __ldg((const float4*)agg + (size_t)(r0 + row) * 32 + c4);
            *(float4*)&Ash[row * AS_STRIDE + c4 * 4] = v;
        }
    }
    __syncthreads();

    unsigned long long acc2[8][4];
#pragma unroll
    for (int i = 0; i < 8; i++)
#pragma unroll
        for (int m = 0; m < 4; m++) acc2[i][m] = 0ULL;

#pragma unroll 4
    for (int kp = 0; kp < DD / 2; kp++) {
        int k = kp * 2;
        unsigned long long w2[4];
#pragma unroll
        for (int m = 0; m < 4; m++)
            w2[m] = *(const unsigned long long*)&WshT[(tx + 32 * m) * WT_STRIDE + k];
#pragma unroll
        for (int i = 0; i < 8; i++) {
            unsigned long long a2 =
                *(const unsigned long long*)&Ash[(i * 8 + ty) * AS_STRIDE + k];
            asm("fma.rn.f32x2 %0, %1, %2, %0;" : "+l"(acc2[i][0]) : "l"(a2), "l"(w2[0]));
            asm("fma.rn.f32x2 %0, %1, %2, %0;" : "+l"(acc2[i][1]) : "l"(a2), "l"(w2[1]));
            asm("fma.rn.f32x2 %0, %1, %2, %0;" : "+l"(acc2[i][2]) : "l"(a2), "l"(w2[2]));
            asm("fma.rn.f32x2 %0, %1, %2, %0;" : "+l"(acc2[i][3]) : "l"(a2), "l"(w2[3]));
        }
    }

    float bcol[4];
#pragma unroll
    for (int m = 0; m < 4; m++) bcol[m] = __ldg(bias + tx + 32 * m);

#pragma unroll
    for (int i = 0; i < 8; i++) {
        int row = r0 + i * 8 + ty;
        if (row < N) {
            int deg = __ldg(off + row + 1) - __ldg(off + row);
            float invr = 1.0f / (float)(deg + 1);
#pragma unroll
            for (int m = 0; m < 4; m++) {
                unsigned int lo, hi;
                asm("mov.b64 {%0,%1}, %2;" : "=r"(lo), "=r"(hi) : "l"(acc2[i][m]));
                float s = __uint_as_float(lo) + __uint_as_float(hi);
                out[(size_t)row * DD + tx + 32 * m] =
                    fmaxf(s * invr + bcol[m], 0.0f);
            }
        }
    }
}

// ---------------------------------------------------------------------------
extern "C" void kernel_launch(void* const* d_in, const int* in_sizes, int n_in,
                              void* d_out, int out_size) {
    const int*   ann = (const int*)d_in[0];
    const int*   src = (const int*)d_in[1];
    const int*   dst = (const int*)d_in[2];
    const float* emb = (const float*)d_in[3];
    const float* Ws  = (const float*)d_in[4];
    const float* bs  = (const float*)d_in[5];

    int N = in_sizes[0];
    int E = in_sizes[1];
    int L = in_sizes[4] / (DD * DD);

    float *h, *agg;
    int *degi, *off, *cursor, *bsum, *csr;
    cudaGetSymbolAddress((void**)&h,      g_h);
    cudaGetSymbolAddress((void**)&agg,    g_agg);
    cudaGetSymbolAddress((void**)&degi,   g_degi);
    cudaGetSymbolAddress((void**)&off,    g_off);
    cudaGetSymbolAddress((void**)&cursor, g_cursor);
    cudaGetSymbolAddress((void**)&bsum,   g_bsum);
    cudaGetSymbolAddress((void**)&csr,    g_csr);
    float* out = (float*)d_out;

    int nb = (N + 255) / 256;

    // ---- CSR build (once per launch) ----
    zero_degi_kernel<<<nb, 256>>>(degi, N);
    degi_kernel<<<(E + 255) / 256, 256>>>(dst, degi, E);
    scan1_kernel<<<nb, 256>>>(degi, off, bsum, N);
    scan2_kernel<<<1, 512>>>(bsum, nb);
    scan3_kernel<<<nb, 256>>>(off, bsum, N, E);
    cudaMemcpyAsync(cursor, off, (size_t)N * sizeof(int),
                    cudaMemcpyDeviceToDevice, 0);
    place_kernel<<<(E + 255) / 256, 256>>>(src, dst, cursor, csr, E);

    // ---- h0 = emb[annotation] ----
    {
        long long t = (long long)N * 32;
        embed_kernel<<<(unsigned)((t + 255) / 256), 256>>>(ann, (const float4*)emb,
                                                           (float4*)h, N);
    }

    size_t shbytes = (size_t)(DD * WT_STRIDE + TILE_R * AS_STRIDE) * sizeof(float);
    cudaFuncSetAttribute(layer_kernel, cudaFuncAttributeMaxDynamicSharedMemorySize,
                         (int)shbytes);

    dim3 blk(32, 8);
    int gemm_blocks = (N + TILE_R - 1) / TILE_R;
    long long ga_threads = (long long)N * 32;
    unsigned ga_blocks = (unsigned)((ga_threads + 255) / 256);

    for (int l = 0; l < L; l++) {
        gather_kernel<<<ga_blocks, 256>>>((const float4*)h, (float4*)agg, off, csr, N);
        float* dstbuf = (l == L - 1) ? out : h;
        layer_kernel<<<gemm_blocks, blk, shbytes>>>(agg, off,
                                                    Ws + (size_t)l * DD * DD,
                                                    bs + (size_t)l * DD,
                                                    dstbuf, N);
    }
}

// round 6
// speedup vs baseline: 1.1045x; 1.1045x over previous
#include <cuda_runtime.h>
#include <cuda_bf16.h>
#include <cstdint>

#define DD 128
#define MAX_N 100000
#define MAX_E 1600000
#define TILE_R 64
#define AS_STRIDE 132   // A tile row stride (floats), float4-aligned rows
#define WS_STRIDE 132   // W tile row stride (floats), float4-aligned rows

// Scratch (device globals — no allocation allowed)
__device__ float g_h[(size_t)MAX_N * DD];
__device__ float g_agg[(size_t)MAX_N * DD];
__device__ int   g_degi[MAX_N];
__device__ int   g_off[MAX_N + 1];
__device__ int   g_cursor[MAX_N];
__device__ int   g_bsum[1024];
__device__ int   g_csr[MAX_E];

// ---------------------------------------------------------------------------
__global__ void zero_degi_kernel(int* __restrict__ degi, int N) {
    int i = blockIdx.x * blockDim.x + threadIdx.x;
    if (i < N) degi[i] = 0;
}

__global__ void degi_kernel(const int* __restrict__ dst, int* __restrict__ degi, int E) {
    int e = blockIdx.x * blockDim.x + threadIdx.x;
    if (e < E) atomicAdd(degi + dst[e], 1);
}

// Block-local exclusive scan (Hillis-Steele in smem), emits block sums
__global__ void scan1_kernel(const int* __restrict__ degi, int* __restrict__ off,
                             int* __restrict__ bsum, int N) {
    __shared__ int s[256];
    int t = threadIdx.x;
    int i = blockIdx.x * 256 + t;
    int v = (i < N) ? degi[i] : 0;
    s[t] = v;
    __syncthreads();
#pragma unroll
    for (int d = 1; d < 256; d <<= 1) {
        int add = (t >= d) ? s[t - d] : 0;
        __syncthreads();
        s[t] += add;
        __syncthreads();
    }
    if (i < N) off[i] = s[t] - v;            // exclusive
    if (t == 255) bsum[blockIdx.x] = s[255]; // block total
}

__global__ void scan2_kernel(int* __restrict__ bsum, int nb) {
    __shared__ int s[512];
    int t = threadIdx.x;
    int v = (t < nb) ? bsum[t] : 0;
    s[t] = v;
    __syncthreads();
#pragma unroll
    for (int d = 1; d < 512; d <<= 1) {
        int add = (t >= d) ? s[t - d] : 0;
        __syncthreads();
        s[t] += add;
        __syncthreads();
    }
    if (t < nb) bsum[t] = s[t] - v;
}

__global__ void scan3_kernel(int* __restrict__ off, const int* __restrict__ bsum,
                             int N, int E) {
    int i = blockIdx.x * 256 + threadIdx.x;
    if (i < N) off[i] += bsum[blockIdx.x];
    if (i == 0) off[N] = E;
}

__global__ void place_kernel(const int* __restrict__ src, const int* __restrict__ dst,
                             int* __restrict__ cursor, int* __restrict__ csr, int E) {
    int e = blockIdx.x * blockDim.x + threadIdx.x;
    if (e >= E) return;
    int pos = atomicAdd(cursor + dst[e], 1);
    csr[pos] = src[e];
}

// h[n][:] = emb[annotation[n]][:]   (one warp per node, float4 lanes)
__global__ void embed_kernel(const int* __restrict__ ann,
                             const float4* __restrict__ emb,
                             float4* __restrict__ h, int N) {
    int gid = blockIdx.x * blockDim.x + threadIdx.x;
    int n = gid >> 5;
    int lane = gid & 31;
    if (n >= N) return;
    int a = __ldg(ann + n);
    h[(size_t)n * 32 + lane] = __ldg(emb + (size_t)a * 32 + lane);
}

// agg[n] = h[n] + sum_{s in in-neighbors(n)} h[s]   (warp per node, no atomics)
__global__ void gather_kernel(const float4* __restrict__ h,
                              float4* __restrict__ agg,
                              const int* __restrict__ off,
                              const int* __restrict__ csr, int N) {
    int gid = blockIdx.x * blockDim.x + threadIdx.x;
    int n = gid >> 5;
    int lane = gid & 31;
    if (n >= N) return;
    int beg = __ldg(off + n);
    int end = __ldg(off + n + 1);
    float4 acc = __ldg(h + (size_t)n * 32 + lane);   // self term
    int i = beg;
    for (; i + 4 <= end; i += 4) {
        int s0 = __ldg(csr + i);
        int s1 = __ldg(csr + i + 1);
        int s2 = __ldg(csr + i + 2);
        int s3 = __ldg(csr + i + 3);
        float4 v0 = __ldg(h + (size_t)s0 * 32 + lane);
        float4 v1 = __ldg(h + (size_t)s1 * 32 + lane);
        float4 v2 = __ldg(h + (size_t)s2 * 32 + lane);
        float4 v3 = __ldg(h + (size_t)s3 * 32 + lane);
        acc.x += v0.x + v1.x + v2.x + v3.x;
        acc.y += v0.y + v1.y + v2.y + v3.y;
        acc.z += v0.z + v1.z + v2.z + v3.z;
        acc.w += v0.w + v1.w + v2.w + v3.w;
    }
    for (; i < end; i++) {
        int s = __ldg(csr + i);
        float4 v = __ldg(h + (size_t)s * 32 + lane);
        acc.x += v.x; acc.y += v.y; acc.z += v.z; acc.w += v.w;
    }
    agg[(size_t)n * 32 + lane] = acc;
}

// out[r][:] = relu( (agg[r][:] / (deg[r]+1)) @ W + b ),  deg from CSR offsets
// f32x2 GEMM, packed over COLUMNS: thread (tx,ty) owns rows {ty,ty+8,...,ty+56}
// and cols {4tx..4tx+3} as two (c,c+1) pairs. W stays row-major in smem; the
// per-k W read is one conflict-free LDS.128; A is a broadcast scalar splatted
// into both halves via one mov.b64 on the alu pipe.
__global__ void layer_kernel(const float* __restrict__ agg,
                             const int* __restrict__ off,
                             const float* __restrict__ W,
                             const float* __restrict__ bias,
                             float* __restrict__ out, int N) {
    extern __shared__ float sh[];
    float* Wsh = sh;                        // DD rows x WS_STRIDE
    float* Ash = sh + DD * WS_STRIDE;       // TILE_R x AS_STRIDE

    int tx = threadIdx.x;                   // 0..31
    int ty = threadIdx.y;                   // 0..7
    int tid = ty * 32 + tx;
    int r0 = blockIdx.x * TILE_R;

    // Load W row-major into smem (stride WS_STRIDE)
    {
        const float4* Wg = (const float4*)W;
#pragma unroll
        for (int j = 0; j < (DD * DD / 4) / 256; j++) {
            int idx = tid + j * 256;        // = k*32 + c4
            int k  = idx >> 5;
            int c4 = idx & 31;
            *(float4*)&Wsh[k * WS_STRIDE + c4 * 4] = __ldg(Wg + idx);
        }
    }
    // Load A tile
    {
#pragma unroll
        for (int j = 0; j < (TILE_R * 32) / 256; j++) {
            int idx = tid + j * 256;
            int row = idx >> 5;
            int c4  = idx & 31;
            float4 v = make_float4(0.f, 0.f, 0.f, 0.f);
            if (r0 + row < N)
                v = __ldg((const float4*)agg + (size_t)(r0 + row) * 32 + c4);
            *(float4*)&Ash[row * AS_STRIDE + c4 * 4] = v;
        }
    }
    __syncthreads();

    unsigned long long acc2[8][2];
#pragma unroll
    for (int i = 0; i < 8; i++) {
        acc2[i][0] = 0ULL;
        acc2[i][1] = 0ULL;
    }

#pragma unroll 8
    for (int k = 0; k < DD; k++) {
        float4 wv = *(const float4*)&Wsh[k * WS_STRIDE + tx * 4];
        unsigned long long w2a, w2b;
        asm("mov.b64 %0, {%1,%2};" : "=l"(w2a) : "f"(wv.x), "f"(wv.y));
        asm("mov.b64 %0, {%1,%2};" : "=l"(w2b) : "f"(wv.z), "f"(wv.w));
#pragma unroll
        for (int i = 0; i < 8; i++) {
            float a = Ash[(i * 8 + ty) * AS_STRIDE + k];
            unsigned long long a2;
            asm("mov.b64 %0, {%1,%1};" : "=l"(a2) : "f"(a));
            asm("fma.rn.f32x2 %0, %1, %2, %0;" : "+l"(acc2[i][0]) : "l"(a2), "l"(w2a));
            asm("fma.rn.f32x2 %0, %1, %2, %0;" : "+l"(acc2[i][1]) : "l"(a2), "l"(w2b));
        }
    }

    float4 b4 = __ldg((const float4*)bias + tx);

#pragma unroll
    for (int i = 0; i < 8; i++) {
        int row = r0 + i * 8 + ty;
        if (row < N) {
            int deg = __ldg(off + row + 1) - __ldg(off + row);
            float invr = 1.0f / (float)(deg + 1);
            unsigned int l0, h0, l1, h1;
            asm("mov.b64 {%0,%1}, %2;" : "=r"(l0), "=r"(h0) : "l"(acc2[i][0]));
            asm("mov.b64 {%0,%1}, %2;" : "=r"(l1), "=r"(h1) : "l"(acc2[i][1]));
            float4 o;
            o.x = fmaxf(__uint_as_float(l0) * invr + b4.x, 0.0f);
            o.y = fmaxf(__uint_as_float(h0) * invr + b4.y, 0.0f);
            o.z = fmaxf(__uint_as_float(l1) * invr + b4.z, 0.0f);
            o.w = fmaxf(__uint_as_float(h1) * invr + b4.w, 0.0f);
            *(float4*)(out + (size_t)row * DD + tx * 4) = o;
        }
    }
}

// ---------------------------------------------------------------------------
extern "C" void kernel_launch(void* const* d_in, const int* in_sizes, int n_in,
                              void* d_out, int out_size) {
    const int*   ann = (const int*)d_in[0];
    const int*   src = (const int*)d_in[1];
    const int*   dst = (const int*)d_in[2];
    const float* emb = (const float*)d_in[3];
    const float* Ws  = (const float*)d_in[4];
    const float* bs  = (const float*)d_in[5];

    int N = in_sizes[0];
    int E = in_sizes[1];
    int L = in_sizes[4] / (DD * DD);

    float *h, *agg;
    int *degi, *off, *cursor, *bsum, *csr;
    cudaGetSymbolAddress((void**)&h,      g_h);
    cudaGetSymbolAddress((void**)&agg,    g_agg);
    cudaGetSymbolAddress((void**)&degi,   g_degi);
    cudaGetSymbolAddress((void**)&off,    g_off);
    cudaGetSymbolAddress((void**)&cursor, g_cursor);
    cudaGetSymbolAddress((void**)&bsum,   g_bsum);
    cudaGetSymbolAddress((void**)&csr,    g_csr);
    float* out = (float*)d_out;

    int nb = (N + 255) / 256;

    // ---- CSR build (once per launch) ----
    zero_degi_kernel<<<nb, 256>>>(degi, N);
    degi_kernel<<<(E + 255) / 256, 256>>>(dst, degi, E);
    scan1_kernel<<<nb, 256>>>(degi, off, bsum, N);
    scan2_kernel<<<1, 512>>>(bsum, nb);
    scan3_kernel<<<nb, 256>>>(off, bsum, N, E);
    cudaMemcpyAsync(cursor, off, (size_t)N * sizeof(int),
                    cudaMemcpyDeviceToDevice, 0);
    place_kernel<<<(E + 255) / 256, 256>>>(src, dst, cursor, csr, E);

    // ---- h0 = emb[annotation] ----
    {
        long long t = (long long)N * 32;
        embed_kernel<<<(unsigned)((t + 255) / 256), 256>>>(ann, (const float4*)emb,
                                                           (float4*)h, N);
    }

    size_t shbytes = (size_t)(DD * WS_STRIDE + TILE_R * AS_STRIDE) * sizeof(float);
    cudaFuncSetAttribute(layer_kernel, cudaFuncAttributeMaxDynamicSharedMemorySize,
                         (int)shbytes);

    dim3 blk(32, 8);
    int gemm_blocks = (N + TILE_R - 1) / TILE_R;
    long long ga_threads = (long long)N * 32;
    unsigned ga_blocks = (unsigned)((ga_threads + 255) / 256);

    for (int l = 0; l < L; l++) {
        gather_kernel<<<ga_blocks, 256>>>((const float4*)h, (float4*)agg, off, csr, N);
        float* dstbuf = (l == L - 1) ? out : h;
        layer_kernel<<<gemm_blocks, blk, shbytes>>>(agg, off,
                                                    Ws + (size_t)l * DD * DD,
                                                    bs + (size_t)l * DD,
                                                    dstbuf, N);
    }
}